// round 2
// baseline (speedup 1.0000x reference)
#include <cuda_runtime.h>
#include <cstdint>

typedef unsigned long long ull;

// ---------------------------------------------------------------------------
// Packed fp32x2 helpers (Blackwell f32x2 pipe; ptxas will not auto-fuse these)
// ---------------------------------------------------------------------------
__device__ __forceinline__ ull pack2(float x, float y) {
    ull r; asm("mov.b64 %0, {%1,%2};" : "=l"(r) : "f"(x), "f"(y)); return r;
}
__device__ __forceinline__ float2 unpack2(ull v) {
    float2 r; asm("mov.b64 {%0,%1}, %2;" : "=f"(r.x), "=f"(r.y) : "l"(v)); return r;
}
__device__ __forceinline__ ull fma2(ull a, ull b, ull c) {
    ull d; asm("fma.rn.f32x2 %0, %1, %2, %3;" : "=l"(d) : "l"(a), "l"(b), "l"(c)); return d;
}

// ---------------------------------------------------------------------------
// Problem constants
// ---------------------------------------------------------------------------
#define NPAIRS 64      // B*heads = 8*8
#define NSEQ   4096    // H*W
#define DD     64      // head_dim

// Kernel 1 (KV pass)
#define SPLITS 16
#define TILE1  128
#define RS1    130     // 128 + 2 pad floats -> bank-pair stride 65 (==1 mod 16)
#define TILES1 2       // 4096 / SPLITS / TILE1

// Kernel 2 (Q/output pass)
#define TILE2  256
#define RS2    258

// Scratch (device globals: no allocations allowed)
__device__ float g_scratch[NPAIRS * SPLITS * DD * DD];  // 16 MB
__device__ float g_kv[NPAIRS * DD * DD];                // 1 MB

// ---------------------------------------------------------------------------
// Kernel 1: per (pair, split): KF = relu(Wf@Ktile + b); KVpartial += KF @ V^T
// ---------------------------------------------------------------------------
__global__ void __launch_bounds__(256, 2)
k_kvpass(const float* __restrict__ K, const float* __restrict__ V,
         const float* __restrict__ Wf, const float* __restrict__ bf)
{
    extern __shared__ float sm1[];
    float* Ks  = sm1;                 // 64 * RS1  (K tile, then overwritten by KF)
    float* Vs  = Ks + 64 * RS1;       // 64 * RS1
    float* Wfs = Vs + 64 * RS1;       // 4096
    float* bfs = Wfs + 4096;          // 64

    const int p     = blockIdx.y;
    const int split = blockIdx.x;
    const int t     = threadIdx.x;
    const int w     = t >> 5;
    const int l     = t & 31;

    for (int i = t; i < 4096; i += 256) Wfs[i] = Wf[i];
    if (t < 64) bfs[t] = bf[t];

    const float* Kb = K + (size_t)p * DD * NSEQ;
    const float* Vb = V + (size_t)p * DD * NSEQ;

    // phase-2 output mapping: KV[e][e2], e = eg + 16i, e2 = e2g + 16j
    const int eg  = t >> 4;   // 0..15
    const int e2g = t & 15;   // 0..15

    ull kvacc[4][4];
    #pragma unroll
    for (int i = 0; i < 4; ++i)
        #pragma unroll
        for (int j = 0; j < 4; ++j) kvacc[i][j] = 0ull;

    for (int tile = 0; tile < TILES1; ++tile) {
        const int n0 = split * (TILE1 * TILES1) + tile * TILE1;
        __syncthreads();  // protect Ks/Vs reuse (covers Wfs/bfs init on iter 0)

        // cooperative coalesced tile load: 64 rows x 128 cols, float4 gmem reads
        for (int m = t; m < 64 * 32; m += 256) {
            const int row = m >> 5;
            const int c4  = (m & 31) << 2;
            float4 kk = *(const float4*)(Kb + row * NSEQ + n0 + c4);
            float4 vv = *(const float4*)(Vb + row * NSEQ + n0 + c4);
            float2* dk = (float2*)&Ks[row * RS1 + c4];
            dk[0] = make_float2(kk.x, kk.y);
            dk[1] = make_float2(kk.z, kk.w);
            float2* dv = (float2*)&Vs[row * RS1 + c4];
            dv[0] = make_float2(vv.x, vv.y);
            dv[1] = make_float2(vv.z, vv.w);
        }
        __syncthreads();

        // phase 1: KF[e][n] = relu(sum_d Wf[e][d]*K[d][n] + b[e])
        // thread tile: e = w*8 + i, n = 2l + 64j (j=0..1)
        ull acc1[8][2];
        #pragma unroll
        for (int i = 0; i < 8; ++i) { acc1[i][0] = 0ull; acc1[i][1] = 0ull; }

        #pragma unroll 4
        for (int d = 0; d < 64; ++d) {
            const ull b0 = *(const ull*)&Ks[d * RS1 + 2 * l];
            const ull b1 = *(const ull*)&Ks[d * RS1 + 64 + 2 * l];
            #pragma unroll
            for (int i = 0; i < 8; ++i) {
                const float a  = Wfs[(w * 8 + i) * 64 + d];
                const ull   a2 = pack2(a, a);
                acc1[i][0] = fma2(a2, b0, acc1[i][0]);
                acc1[i][1] = fma2(a2, b1, acc1[i][1]);
            }
        }
        __syncthreads();  // everyone done reading Ks
        #pragma unroll
        for (int i = 0; i < 8; ++i) {
            const float bb = bfs[w * 8 + i];
            #pragma unroll
            for (int j = 0; j < 2; ++j) {
                float2 x = unpack2(acc1[i][j]);
                x.x = fmaxf(x.x + bb, 0.f);
                x.y = fmaxf(x.y + bb, 0.f);
                *(float2*)&Ks[(w * 8 + i) * RS1 + 64 * j + 2 * l] = x;  // KF in-place
            }
        }
        __syncthreads();

        // phase 2: KV[e][e2] += sum_n KF[e][n] * V[e2][n]  (n packed in pairs)
        #pragma unroll 4
        for (int np = 0; np < 64; ++np) {
            ull a2[4], b2[4];
            #pragma unroll
            for (int i = 0; i < 4; ++i)
                a2[i] = *(const ull*)&Ks[(eg + 16 * i) * RS1 + 2 * np];
            #pragma unroll
            for (int j = 0; j < 4; ++j)
                b2[j] = *(const ull*)&Vs[(e2g + 16 * j) * RS1 + 2 * np];
            #pragma unroll
            for (int i = 0; i < 4; ++i)
                #pragma unroll
                for (int j = 0; j < 4; ++j)
                    kvacc[i][j] = fma2(a2[i], b2[j], kvacc[i][j]);
        }
    }

    float* dst = g_scratch + ((size_t)p * SPLITS + split) * DD * DD;
    #pragma unroll
    for (int i = 0; i < 4; ++i)
        #pragma unroll
        for (int j = 0; j < 4; ++j) {
            float2 x = unpack2(kvacc[i][j]);
            dst[(eg + 16 * i) * DD + (e2g + 16 * j)] = x.x + x.y;
        }
}

// ---------------------------------------------------------------------------
// Kernel 2: deterministic fixed-order reduction of split partials
// ---------------------------------------------------------------------------
__global__ void k_reduce()
{
    const int idx = blockIdx.x * 256 + threadIdx.x;   // 0 .. 64*4096-1
    const int p = idx >> 12;
    const int r = idx & 4095;
    float s = 0.f;
    #pragma unroll
    for (int sp = 0; sp < SPLITS; ++sp)
        s += g_scratch[((size_t)p * SPLITS + sp) * (DD * DD) + r];
    g_kv[idx] = s;
}

// ---------------------------------------------------------------------------
// Kernel 3: QF = relu(Wf@Qtile + b); O = KV^T @ QF, written to output layout
// ---------------------------------------------------------------------------
__global__ void __launch_bounds__(256, 2)
k_qpass(const float* __restrict__ Q, const float* __restrict__ Wf,
        const float* __restrict__ bf, float* __restrict__ Out)
{
    extern __shared__ float sm2[];
    float* buf = sm2;               // 64 * RS2 (Q tile, then QF in-place)
    float* Wfs = buf + 64 * RS2;    // 4096
    float* KVs = Wfs + 4096;        // 4096
    float* bfs = KVs + 4096;        // 64

    const int p  = blockIdx.y;
    const int n0 = blockIdx.x * TILE2;
    const int t  = threadIdx.x;
    const int w  = t >> 5;
    const int l  = t & 31;

    for (int i = t; i < 4096; i += 256) {
        Wfs[i] = Wf[i];
        KVs[i] = g_kv[(size_t)p * 4096 + i];
    }
    if (t < 64) bfs[t] = bf[t];

    const float* Qb = Q + (size_t)p * DD * NSEQ;

    // load Q tile [64][256]
    for (int m = t; m < 64 * 64; m += 256) {
        const int row = m >> 6;
        const int c4  = (m & 63) << 2;
        float4 qq = *(const float4*)(Qb + row * NSEQ + n0 + c4);
        float2* dq = (float2*)&buf[row * RS2 + c4];
        dq[0] = make_float2(qq.x, qq.y);
        dq[1] = make_float2(qq.z, qq.w);
    }
    __syncthreads();

    // phase 1: QF[e][n], thread tile e = w*8+i, n = 2l + 64j (j=0..3)
    ull acc[8][4];
    #pragma unroll
    for (int i = 0; i < 8; ++i)
        #pragma unroll
        for (int j = 0; j < 4; ++j) acc[i][j] = 0ull;

    #pragma unroll 2
    for (int d = 0; d < 64; ++d) {
        ull b2[4];
        #pragma unroll
        for (int j = 0; j < 4; ++j)
            b2[j] = *(const ull*)&buf[d * RS2 + 64 * j + 2 * l];
        #pragma unroll
        for (int i = 0; i < 8; ++i) {
            const float a  = Wfs[(w * 8 + i) * 64 + d];
            const ull   a2 = pack2(a, a);
            #pragma unroll
            for (int j = 0; j < 4; ++j)
                acc[i][j] = fma2(a2, b2[j], acc[i][j]);
        }
    }
    __syncthreads();
    #pragma unroll
    for (int i = 0; i < 8; ++i) {
        const float bb = bfs[w * 8 + i];
        #pragma unroll
        for (int j = 0; j < 4; ++j) {
            float2 x = unpack2(acc[i][j]);
            x.x = fmaxf(x.x + bb, 0.f);
            x.y = fmaxf(x.y + bb, 0.f);
            *(float2*)&buf[(w * 8 + i) * RS2 + 64 * j + 2 * l] = x;  // QF in-place
        }
    }
    __syncthreads();

    // phase 2: O[e2][n] = sum_e KV[e][e2] * QF[e][n], e2 = w*8+i
    ull o[8][4];
    #pragma unroll
    for (int i = 0; i < 8; ++i)
        #pragma unroll
        for (int j = 0; j < 4; ++j) o[i][j] = 0ull;

    #pragma unroll 2
    for (int e = 0; e < 64; ++e) {
        ull b2[4];
        #pragma unroll
        for (int j = 0; j < 4; ++j)
            b2[j] = *(const ull*)&buf[e * RS2 + 64 * j + 2 * l];
        #pragma unroll
        for (int i = 0; i < 8; ++i) {
            const float a  = KVs[e * 64 + w * 8 + i];
            const ull   a2 = pack2(a, a);
            #pragma unroll
            for (int j = 0; j < 4; ++j)
                o[i][j] = fma2(a2, b2[j], o[i][j]);
        }
    }

    float* Ob = Out + (size_t)p * DD * NSEQ;
    #pragma unroll
    for (int i = 0; i < 8; ++i)
        #pragma unroll
        for (int j = 0; j < 4; ++j)
            *(float2*)(Ob + (w * 8 + i) * NSEQ + n0 + 64 * j + 2 * l) = unpack2(o[i][j]);
}

// ---------------------------------------------------------------------------
// Launch
// ---------------------------------------------------------------------------
extern "C" void kernel_launch(void* const* d_in, const int* in_sizes, int n_in,
                              void* d_out, int out_size)
{
    const float* q  = (const float*)d_in[0];
    const float* k  = (const float*)d_in[1];
    const float* v  = (const float*)d_in[2];
    const float* Wf = (const float*)d_in[3];
    const float* bf = (const float*)d_in[4];
    float* out = (float*)d_out;

    const int SMEM1 = (2 * 64 * RS1 + 4096 + 64) * (int)sizeof(float);          // ~83 KB
    const int SMEM2 = (64 * RS2 + 4096 + 4096 + 64) * (int)sizeof(float);       // ~97 KB
    cudaFuncSetAttribute(k_kvpass, cudaFuncAttributeMaxDynamicSharedMemorySize, SMEM1);
    cudaFuncSetAttribute(k_qpass,  cudaFuncAttributeMaxDynamicSharedMemorySize, SMEM2);

    k_kvpass<<<dim3(SPLITS, NPAIRS), 256, SMEM1>>>(k, v, Wf, bf);
    k_reduce<<<(NPAIRS * DD * DD) / 256, 256>>>();
    k_qpass<<<dim3(NSEQ / TILE2, NPAIRS), 256, SMEM2>>>(q, Wf, bf, out);
}

// round 5
// speedup vs baseline: 1.3992x; 1.3992x over previous
#include <cuda_runtime.h>
#include <cstdint>

// ---------------------------------------------------------------------------
// Problem constants
// ---------------------------------------------------------------------------
#define NPAIRS 64      // B*heads = 8*8
#define NSEQ   4096    // H*W
#define DD     64      // head_dim
#define SPLITS 16

#define RSK 132        // tile row stride: 132 % 32 == 4 -> k-major B loads conflict-free
#define RSQ 260        // Q tile row stride: 260 % 32 == 4
#define RSA 68         // 64x64 matrix stride (even -> float2-aligned)

// Scratch (device globals: no allocations allowed)
__device__ float g_scratch[NPAIRS * SPLITS * DD * DD];  // 16 MB
__device__ float g_kv[NPAIRS * DD * DD];                // 1 MB

// ---------------------------------------------------------------------------
// bf16 split helpers (Markidis-style 3-term compensation)
// ---------------------------------------------------------------------------
__device__ __forceinline__ uint32_t bf2(float lo, float hi) {
    // d[31:16] = bf16(hi), d[15:0] = bf16(lo)
    uint32_t r;
    asm("cvt.rn.bf16x2.f32 %0, %1, %2;" : "=r"(r) : "f"(hi), "f"(lo));
    return r;
}
// Split packed pair (x0,x1) into hi bf16x2 and residual-lo bf16x2
__device__ __forceinline__ void split2(float x0, float x1, uint32_t& h, uint32_t& l) {
    h = bf2(x0, x1);
    float h0 = __uint_as_float(h << 16);
    float h1 = __uint_as_float(h & 0xFFFF0000u);
    l = bf2(x0 - h0, x1 - h1);
}

__device__ __forceinline__ void mma_bf16(float* d, const uint32_t* a, const uint32_t* b) {
    asm volatile(
        "mma.sync.aligned.m16n8k16.row.col.f32.bf16.bf16.f32 "
        "{%0,%1,%2,%3}, {%4,%5,%6,%7}, {%8,%9}, {%0,%1,%2,%3};"
        : "+f"(d[0]), "+f"(d[1]), "+f"(d[2]), "+f"(d[3])
        : "r"(a[0]), "r"(a[1]), "r"(a[2]), "r"(a[3]), "r"(b[0]), "r"(b[1]));
}
// d += a*b with ~2^-16 relative precision (drop al*bl)
__device__ __forceinline__ void mma3(float* d, const uint32_t* ah, const uint32_t* al,
                                     const uint32_t* bh, const uint32_t* bl) {
    mma_bf16(d, al, bh);
    mma_bf16(d, ah, bl);
    mma_bf16(d, ah, bh);
}

// A fragment (row-major, rows r0/r1, k-cols [kb+2q, kb+2q+1] and +8)
__device__ __forceinline__ void loadA(const float* M, int S, int r0, int r1, int kq,
                                      uint32_t* ah, uint32_t* al) {
    float2 f0 = *(const float2*)&M[r0 * S + kq];
    float2 f1 = *(const float2*)&M[r1 * S + kq];
    float2 f2 = *(const float2*)&M[r0 * S + kq + 8];
    float2 f3 = *(const float2*)&M[r1 * S + kq + 8];
    split2(f0.x, f0.y, ah[0], al[0]);
    split2(f1.x, f1.y, ah[1], al[1]);
    split2(f2.x, f2.y, ah[2], al[2]);
    split2(f3.x, f3.y, ah[3], al[3]);
}
// B fragment from k-major storage (row = k, col = n): scalar loads
__device__ __forceinline__ void loadB_k(const float* M, int S, int kq, int c,
                                        uint32_t* bh, uint32_t* bl) {
    split2(M[kq * S + c],       M[(kq + 1) * S + c], bh[0], bl[0]);
    split2(M[(kq + 8) * S + c], M[(kq + 9) * S + c], bh[1], bl[1]);
}
// B fragment from n-major storage (row = n-index, contiguous k): float2 loads
__device__ __forceinline__ void loadB_n(const float* M, int S, int row, int kq,
                                        uint32_t* bh, uint32_t* bl) {
    float2 f0 = *(const float2*)&M[row * S + kq];
    float2 f1 = *(const float2*)&M[row * S + kq + 8];
    split2(f0.x, f0.y, bh[0], bl[0]);
    split2(f1.x, f1.y, bh[1], bl[1]);
}

// ---------------------------------------------------------------------------
// Kernel 1: per (pair, split): KF = relu(Wf@Ktile + b); KVpartial += KF @ V^T
// ---------------------------------------------------------------------------
__global__ void __launch_bounds__(256, 2)
k_kvpass(const float* __restrict__ K, const float* __restrict__ V,
         const float* __restrict__ Wf, const float* __restrict__ bf)
{
    extern __shared__ float sm1[];
    float* Ks  = sm1;                  // 64 * RSK (K tile, then KF in-place)
    float* Vs  = Ks + 64 * RSK;        // 64 * RSK
    float* Wfs = Vs + 64 * RSK;        // 64 * RSA
    float* bfs = Wfs + 64 * RSA;       // 64

    const int p     = blockIdx.y;
    const int split = blockIdx.x;
    const int t     = threadIdx.x;
    const int w     = t >> 5;
    const int lane  = t & 31;
    const int g     = lane >> 2;       // groupID 0..7
    const int q2    = (lane & 3) * 2;  // 2*threadID_in_group
    const int mstrip = w & 3;
    const int nh     = w >> 2;         // 0/1
    const int r0 = mstrip * 16 + g;
    const int r1 = r0 + 8;

    for (int i = t; i < 64 * 64; i += 256) Wfs[(i >> 6) * RSA + (i & 63)] = Wf[i];
    if (t < 64) bfs[t] = bf[t];

    const float* Kb = K + (size_t)p * DD * NSEQ;
    const float* Vb = V + (size_t)p * DD * NSEQ;

    float kv[4][4];
    #pragma unroll
    for (int i = 0; i < 4; ++i)
        #pragma unroll
        for (int j = 0; j < 4; ++j) kv[i][j] = 0.f;

    for (int tile = 0; tile < 2; ++tile) {
        const int n0 = split * 256 + tile * 128;
        __syncthreads();   // protect Ks/Vs reuse (covers Wfs/bfs init on iter 0)

        for (int m = t; m < 64 * 32; m += 256) {
            const int row = m >> 5;
            const int c4  = (m & 31) << 2;
            *(float4*)&Ks[row * RSK + c4] = *(const float4*)(Kb + row * NSEQ + n0 + c4);
            *(float4*)&Vs[row * RSK + c4] = *(const float4*)(Vb + row * NSEQ + n0 + c4);
        }
        __syncthreads();

        // ---- GEMM1: KF = Wf @ Ktile (M=64, N=128, K=64) ----
        float acc[8][4];
        #pragma unroll
        for (int i = 0; i < 8; ++i)
            #pragma unroll
            for (int j = 0; j < 4; ++j) acc[i][j] = 0.f;

        #pragma unroll
        for (int ks = 0; ks < 4; ++ks) {
            const int kq = ks * 16 + q2;
            uint32_t ah[4], al[4];
            loadA(Wfs, RSA, r0, r1, kq, ah, al);
            #pragma unroll
            for (int nf = 0; nf < 8; ++nf) {
                const int c = nh * 64 + nf * 8 + g;
                uint32_t bh[2], bl[2];
                loadB_k(Ks, RSK, kq, c, bh, bl);
                mma3(acc[nf], ah, al, bh, bl);
            }
        }
        __syncthreads();   // all warps done reading Ks
        {
            const float b0 = bfs[r0], b1 = bfs[r1];
            #pragma unroll
            for (int nf = 0; nf < 8; ++nf) {
                const int nb = nh * 64 + nf * 8 + q2;
                *(float2*)&Ks[r0 * RSK + nb] =
                    make_float2(fmaxf(acc[nf][0] + b0, 0.f), fmaxf(acc[nf][1] + b0, 0.f));
                *(float2*)&Ks[r1 * RSK + nb] =
                    make_float2(fmaxf(acc[nf][2] + b1, 0.f), fmaxf(acc[nf][3] + b1, 0.f));
            }
        }
        __syncthreads();

        // ---- GEMM2: KV += KF @ V^T (M=64, N=64, K=128) ----
        #pragma unroll 4
        for (int ks = 0; ks < 8; ++ks) {
            const int kq = ks * 16 + q2;
            uint32_t ah[4], al[4];
            loadA(Ks, RSK, r0, r1, kq, ah, al);    // A = KF rows e, contiguous n
            #pragma unroll
            for (int ef = 0; ef < 4; ++ef) {
                const int row = nh * 32 + ef * 8 + g;  // e2 index
                uint32_t bh[2], bl[2];
                loadB_n(Vs, RSK, row, kq, bh, bl);     // B[k=n][e2] = V[e2][n]
                mma3(kv[ef], ah, al, bh, bl);
            }
        }
    }

    float* dst = g_scratch + ((size_t)p * SPLITS + split) * DD * DD;
    #pragma unroll
    for (int ef = 0; ef < 4; ++ef) {
        const int c = nh * 32 + ef * 8 + q2;
        *(float2*)&dst[r0 * DD + c] = make_float2(kv[ef][0], kv[ef][1]);
        *(float2*)&dst[r1 * DD + c] = make_float2(kv[ef][2], kv[ef][3]);
    }
}

// ---------------------------------------------------------------------------
// Kernel 2: deterministic fixed-order reduction of split partials
// ---------------------------------------------------------------------------
__global__ void k_reduce()
{
    const int idx = blockIdx.x * 256 + threadIdx.x;   // 0 .. 64*4096-1
    const int pr = idx >> 12;
    const int r  = idx & 4095;
    float s = 0.f;
    #pragma unroll
    for (int sp = 0; sp < SPLITS; ++sp)
        s += g_scratch[((size_t)pr * SPLITS + sp) * (DD * DD) + r];
    g_kv[idx] = s;
}

// ---------------------------------------------------------------------------
// Kernel 3: QF = relu(Wf@Qtile + b); O = KV^T @ QF  (tile N = 256)
// ---------------------------------------------------------------------------
__global__ void __launch_bounds__(256, 2)
k_qpass(const float* __restrict__ Q, const float* __restrict__ Wf,
        const float* __restrict__ bf, float* __restrict__ Out)
{
    extern __shared__ float sm2[];
    float* Qs   = sm2;                  // 64 * RSQ (Q tile, then QF in-place)
    float* Wfs  = Qs + 64 * RSQ;        // 64 * RSA
    float* KVTs = Wfs + 64 * RSA;       // 64 * RSA (KV^T: row = e2, col = e)
    float* bfs  = KVTs + 64 * RSA;      // 64

    const int p  = blockIdx.y;
    const int n0 = blockIdx.x * 256;
    const int t    = threadIdx.x;
    const int w    = t >> 5;
    const int lane = t & 31;
    const int g    = lane >> 2;
    const int q2   = (lane & 3) * 2;
    const int mstrip = w & 3;
    const int nh     = w >> 2;          // 0/1 (each half = 128 cols)
    const int r0 = mstrip * 16 + g;
    const int r1 = r0 + 8;

    for (int i = t; i < 64 * 64; i += 256) {
        Wfs[(i >> 6) * RSA + (i & 63)]  = Wf[i];
        KVTs[(i & 63) * RSA + (i >> 6)] = g_kv[(size_t)p * 4096 + i];  // transpose
    }
    if (t < 64) bfs[t] = bf[t];

    const float* Qb = Q + (size_t)p * DD * NSEQ;
    for (int m = t; m < 64 * 64; m += 256) {
        const int row = m >> 6;
        const int c4  = (m & 63) << 2;
        *(float4*)&Qs[row * RSQ + c4] = *(const float4*)(Qb + row * NSEQ + n0 + c4);
    }
    __syncthreads();

    // ---- GEMM3: QF = Wf @ Qtile (M=64, N=256, K=64) ----
    float acc[16][4];
    #pragma unroll
    for (int i = 0; i < 16; ++i)
        #pragma unroll
        for (int j = 0; j < 4; ++j) acc[i][j] = 0.f;

    #pragma unroll 2
    for (int ks = 0; ks < 4; ++ks) {
        const int kq = ks * 16 + q2;
        uint32_t ah[4], al[4];
        loadA(Wfs, RSA, r0, r1, kq, ah, al);
        #pragma unroll
        for (int nf = 0; nf < 16; ++nf) {
            const int c = nh * 128 + nf * 8 + g;
            uint32_t bh[2], bl[2];
            loadB_k(Qs, RSQ, kq, c, bh, bl);
            mma3(acc[nf], ah, al, bh, bl);
        }
    }
    __syncthreads();
    {
        const float b0 = bfs[r0], b1 = bfs[r1];
        #pragma unroll
        for (int nf = 0; nf < 16; ++nf) {
            const int nb = nh * 128 + nf * 8 + q2;
            *(float2*)&Qs[r0 * RSQ + nb] =
                make_float2(fmaxf(acc[nf][0] + b0, 0.f), fmaxf(acc[nf][1] + b0, 0.f));
            *(float2*)&Qs[r1 * RSQ + nb] =
                make_float2(fmaxf(acc[nf][2] + b1, 0.f), fmaxf(acc[nf][3] + b1, 0.f));
        }
    }
    __syncthreads();

    // ---- GEMM4: O = KV^T @ QF (M=64, N=256, K=64) ----
    float o[16][4];
    #pragma unroll
    for (int i = 0; i < 16; ++i)
        #pragma unroll
        for (int j = 0; j < 4; ++j) o[i][j] = 0.f;

    #pragma unroll 2
    for (int ks = 0; ks < 4; ++ks) {
        const int kq = ks * 16 + q2;
        uint32_t ah[4], al[4];
        loadA(KVTs, RSA, r0, r1, kq, ah, al);
        #pragma unroll
        for (int nf = 0; nf < 16; ++nf) {
            const int c = nh * 128 + nf * 8 + g;
            uint32_t bh[2], bl[2];
            loadB_k(Qs, RSQ, kq, c, bh, bl);
            mma3(o[nf], ah, al, bh, bl);
        }
    }

    float* Ob = Out + (size_t)p * DD * NSEQ;
    #pragma unroll
    for (int nf = 0; nf < 16; ++nf) {
        const int col = n0 + nh * 128 + nf * 8 + q2;
        *(float2*)&Ob[r0 * NSEQ + col] = make_float2(o[nf][0], o[nf][1]);
        *(float2*)&Ob[r1 * NSEQ + col] = make_float2(o[nf][2], o[nf][3]);
    }
}

// ---------------------------------------------------------------------------
// Launch
// ---------------------------------------------------------------------------
extern "C" void kernel_launch(void* const* d_in, const int* in_sizes, int n_in,
                              void* d_out, int out_size)
{
    const float* q  = (const float*)d_in[0];
    const float* k  = (const float*)d_in[1];
    const float* v  = (const float*)d_in[2];
    const float* Wf = (const float*)d_in[3];
    const float* bf = (const float*)d_in[4];
    float* out = (float*)d_out;

    const int SMEM1 = (2 * 64 * RSK + 64 * RSA + 64) * (int)sizeof(float);     // ~83 KB
    const int SMEM2 = (64 * RSQ + 2 * 64 * RSA + 64) * (int)sizeof(float);     // ~99 KB
    cudaFuncSetAttribute(k_kvpass, cudaFuncAttributeMaxDynamicSharedMemorySize, SMEM1);
    cudaFuncSetAttribute(k_qpass,  cudaFuncAttributeMaxDynamicSharedMemorySize, SMEM2);

    k_kvpass<<<dim3(SPLITS, NPAIRS), 256, SMEM1>>>(k, v, Wf, bf);
    k_reduce<<<(NPAIRS * DD * DD) / 256, 256>>>();
    k_qpass<<<dim3(NSEQ / 256, NPAIRS), 256, SMEM2>>>(q, Wf, bf, out);
}

// round 6
// speedup vs baseline: 1.5263x; 1.0909x over previous
#include <cuda_runtime.h>
#include <cstdint>

// ---------------------------------------------------------------------------
// Problem constants
// ---------------------------------------------------------------------------
#define NPAIRS 64      // B*heads = 8*8
#define NSEQ   4096    // H*W
#define DD     64      // head_dim
#define SPLITS 16

// Scratch (device globals: no allocations allowed)
__device__ float g_scratch[NPAIRS * SPLITS * DD * DD];  // 16 MB
__device__ float g_kv[NPAIRS * DD * DD];                // 1 MB

// ---------------------------------------------------------------------------
// bf16 split helpers (Markidis-style 3-term compensation)
// ---------------------------------------------------------------------------
__device__ __forceinline__ uint32_t bf2(float lo, float hi) {
    // d[31:16] = bf16(hi), d[15:0] = bf16(lo)
    uint32_t r;
    asm("cvt.rn.bf16x2.f32 %0, %1, %2;" : "=r"(r) : "f"(hi), "f"(lo));
    return r;
}
__device__ __forceinline__ void split2(float x0, float x1, uint32_t& h, uint32_t& l) {
    h = bf2(x0, x1);
    float h0 = __uint_as_float(h << 16);
    float h1 = __uint_as_float(h & 0xFFFF0000u);
    l = bf2(x0 - h0, x1 - h1);
}

__device__ __forceinline__ void mma_bf16(float* d, const uint32_t* a, const uint32_t* b) {
    asm volatile(
        "mma.sync.aligned.m16n8k16.row.col.f32.bf16.bf16.f32 "
        "{%0,%1,%2,%3}, {%4,%5,%6,%7}, {%8,%9}, {%0,%1,%2,%3};"
        : "+f"(d[0]), "+f"(d[1]), "+f"(d[2]), "+f"(d[3])
        : "r"(a[0]), "r"(a[1]), "r"(a[2]), "r"(a[3]), "r"(b[0]), "r"(b[1]));
}
// d += a*b, dropping al*bl (rel err ~2^-16)
__device__ __forceinline__ void mma3(float* d, const uint32_t* ah, const uint32_t* al,
                                     const uint32_t* bh, const uint32_t* bl) {
    mma_bf16(d, al, bh);
    mma_bf16(d, ah, bl);
    mma_bf16(d, ah, bh);
}

// ---------------------------------------------------------------------------
// Kernel 1: per (pair, split): KF = relu(Wf@Ktile + b); KVpartial += KF @ V^T
// Pre-split bf16 hi/lo planes in smem; all fragment loads are single LDS.32.
//   Kp  planes [32][136]: u32(dp,n) = (K[2dp][n], K[2dp+1][n])      (B of GEMM1)
//   Wa  planes [64][36] : u32(e,dp) = (Wf[e][2dp], Wf[e][2dp+1])     (A of GEMM1)
//   KF  planes [64][68] : u32(e,np) = (KF[e][2np], KF[e][2np+1])     (A of GEMM2, alias Kp)
//   Vp  planes [64][68] : u32(e2,np) = (V[e2][2np], V[e2][2np+1])    (B of GEMM2)
// ---------------------------------------------------------------------------
__global__ void __launch_bounds__(256, 2)
k_kvpass(const float* __restrict__ K, const float* __restrict__ V,
         const float* __restrict__ Wf, const float* __restrict__ bf)
{
    extern __shared__ uint32_t sm[];
    uint32_t* KpHi = sm;               // 32*136 = 4352
    uint32_t* KpLo = sm + 4352;
    uint32_t* KFHi = sm;               // 64*68 = 4352 (alias, time-separated)
    uint32_t* KFLo = sm + 4352;
    uint32_t* VpHi = sm + 8704;        // 64*68
    uint32_t* VpLo = sm + 13056;
    uint32_t* WaHi = sm + 17408;       // 64*36 = 2304
    uint32_t* WaLo = sm + 19712;
    float*    bfs  = (float*)(sm + 22016);   // 64 -> total 22080 u32 = 88320 B

    const int p     = blockIdx.y;
    const int split = blockIdx.x;
    const int t     = threadIdx.x;
    const int w     = t >> 5;
    const int lane  = t & 31;
    const int g     = lane >> 2;       // groupID 0..7
    const int q     = lane & 3;        // threadID_in_group
    const int mstrip = w & 3;
    const int nh     = w >> 2;         // 0/1 (which 64-col half)
    const int r0 = mstrip * 16 + g;
    const int r1 = r0 + 8;

    // Wf planes (packed along d, row-contiguous reads)
    for (int i = t; i < 64 * 32; i += 256) {
        const int e = i >> 5, dp = i & 31;
        float2 f = *(const float2*)&Wf[e * 64 + 2 * dp];
        uint32_t h, l; split2(f.x, f.y, h, l);
        WaHi[e * 36 + dp] = h; WaLo[e * 36 + dp] = l;
    }
    if (t < 64) bfs[t] = bf[t];

    const float* Kb = K + (size_t)p * DD * NSEQ;
    const float* Vb = V + (size_t)p * DD * NSEQ;

    float kv[4][4];
    #pragma unroll
    for (int i = 0; i < 4; ++i)
        #pragma unroll
        for (int j = 0; j < 4; ++j) kv[i][j] = 0.f;

    for (int tile = 0; tile < 2; ++tile) {
        const int n0 = split * 256 + tile * 128;
        __syncthreads();   // protect Kp/Vp reuse (covers Wa/bfs init on iter 0)

        // K planes: pack along d (2 rows per iter)
        for (int m = t; m < 32 * 32; m += 256) {
            const int dp = m >> 5;
            const int c4 = (m & 31) << 2;
            float4 k0 = *(const float4*)(Kb + (2 * dp)     * NSEQ + n0 + c4);
            float4 k1 = *(const float4*)(Kb + (2 * dp + 1) * NSEQ + n0 + c4);
            uint32_t h[4], l[4];
            split2(k0.x, k1.x, h[0], l[0]);
            split2(k0.y, k1.y, h[1], l[1]);
            split2(k0.z, k1.z, h[2], l[2]);
            split2(k0.w, k1.w, h[3], l[3]);
            *(uint4*)&KpHi[dp * 136 + c4] = make_uint4(h[0], h[1], h[2], h[3]);
            *(uint4*)&KpLo[dp * 136 + c4] = make_uint4(l[0], l[1], l[2], l[3]);
        }
        // V planes: pack along n
        for (int m = t; m < 64 * 32; m += 256) {
            const int row = m >> 5;
            const int c4  = (m & 31) << 2;
            float4 v = *(const float4*)(Vb + row * NSEQ + n0 + c4);
            uint32_t h0, l0, h1, l1;
            split2(v.x, v.y, h0, l0);
            split2(v.z, v.w, h1, l1);
            *(uint2*)&VpHi[row * 68 + (c4 >> 1)] = make_uint2(h0, h1);
            *(uint2*)&VpLo[row * 68 + (c4 >> 1)] = make_uint2(l0, l1);
        }
        __syncthreads();

        // ---- GEMM1: KF = Wf @ Ktile (M=64, N=128, K=64) ----
        float acc[8][4];
        #pragma unroll
        for (int i = 0; i < 8; ++i)
            #pragma unroll
            for (int j = 0; j < 4; ++j) acc[i][j] = 0.f;

        #pragma unroll
        for (int ks = 0; ks < 4; ++ks) {
            const int dp0 = ks * 8 + q;
            uint32_t ah[4], al[4];
            ah[0] = WaHi[r0 * 36 + dp0];     al[0] = WaLo[r0 * 36 + dp0];
            ah[1] = WaHi[r1 * 36 + dp0];     al[1] = WaLo[r1 * 36 + dp0];
            ah[2] = WaHi[r0 * 36 + dp0 + 4]; al[2] = WaLo[r0 * 36 + dp0 + 4];
            ah[3] = WaHi[r1 * 36 + dp0 + 4]; al[3] = WaLo[r1 * 36 + dp0 + 4];
            #pragma unroll
            for (int nf = 0; nf < 8; ++nf) {
                const int c = nh * 64 + nf * 8 + g;
                uint32_t bh[2], bl[2];
                bh[0] = KpHi[dp0 * 136 + c];       bl[0] = KpLo[dp0 * 136 + c];
                bh[1] = KpHi[(dp0 + 4) * 136 + c]; bl[1] = KpLo[(dp0 + 4) * 136 + c];
                mma3(acc[nf], ah, al, bh, bl);
            }
        }
        __syncthreads();   // all warps done reading Kp before KF overwrites it

        // epilogue: bias+relu, split once, store KF planes (packed along n)
        {
            const float b0 = bfs[r0], b1 = bfs[r1];
            #pragma unroll
            for (int nf = 0; nf < 8; ++nf) {
                const int np = nh * 32 + nf * 4 + q;
                uint32_t h, l;
                split2(fmaxf(acc[nf][0] + b0, 0.f), fmaxf(acc[nf][1] + b0, 0.f), h, l);
                KFHi[r0 * 68 + np] = h; KFLo[r0 * 68 + np] = l;
                split2(fmaxf(acc[nf][2] + b1, 0.f), fmaxf(acc[nf][3] + b1, 0.f), h, l);
                KFHi[r1 * 68 + np] = h; KFLo[r1 * 68 + np] = l;
            }
        }
        __syncthreads();

        // ---- GEMM2: KV += KF @ V^T (M=64, N=64, K=128) ----
        #pragma unroll
        for (int ks = 0; ks < 8; ++ks) {
            const int np0 = ks * 8 + q;
            uint32_t ah[4], al[4];
            ah[0] = KFHi[r0 * 68 + np0];     al[0] = KFLo[r0 * 68 + np0];
            ah[1] = KFHi[r1 * 68 + np0];     al[1] = KFLo[r1 * 68 + np0];
            ah[2] = KFHi[r0 * 68 + np0 + 4]; al[2] = KFLo[r0 * 68 + np0 + 4];
            ah[3] = KFHi[r1 * 68 + np0 + 4]; al[3] = KFLo[r1 * 68 + np0 + 4];
            #pragma unroll
            for (int ef = 0; ef < 4; ++ef) {
                const int row = nh * 32 + ef * 8 + g;   // e2 index
                uint32_t bh[2], bl[2];
                bh[0] = VpHi[row * 68 + np0];     bl[0] = VpLo[row * 68 + np0];
                bh[1] = VpHi[row * 68 + np0 + 4]; bl[1] = VpLo[row * 68 + np0 + 4];
                mma3(kv[ef], ah, al, bh, bl);
            }
        }
    }

    float* dst = g_scratch + ((size_t)p * SPLITS + split) * DD * DD;
    #pragma unroll
    for (int ef = 0; ef < 4; ++ef) {
        const int c = nh * 32 + ef * 8 + 2 * q;
        *(float2*)&dst[r0 * DD + c] = make_float2(kv[ef][0], kv[ef][1]);
        *(float2*)&dst[r1 * DD + c] = make_float2(kv[ef][2], kv[ef][3]);
    }
}

// ---------------------------------------------------------------------------
// Kernel 2: deterministic fixed-order reduction of split partials
// ---------------------------------------------------------------------------
__global__ void k_reduce()
{
    const int idx = blockIdx.x * 256 + threadIdx.x;   // 0 .. 64*4096-1
    const int pr = idx >> 12;
    const int r  = idx & 4095;
    float s = 0.f;
    #pragma unroll
    for (int sp = 0; sp < SPLITS; ++sp)
        s += g_scratch[((size_t)pr * SPLITS + sp) * (DD * DD) + r];
    g_kv[idx] = s;
}

// ---------------------------------------------------------------------------
// Kernel 3: transposed formulation, tile n=128 per CTA:
//   GEMM3: QF^T[n][e] = relu( Q^T[n][d] @ Wf^T[d][e] + b[e] )
//   GEMM4: O^T[n][e2] = QF^T[n][e] @ KV[e][e2]
// Planes:
//   Qd [32][136]: u32(dp,n)  = (Q[2dp][n], Q[2dp+1][n])      (A of GEMM3)
//   Wb [32][72] : u32(dp,e)  = (Wf[e][2dp], Wf[e][2dp+1])    (B of GEMM3)
//   QF [128][36]: u32(n,ep)  = (QF^T[n][2ep], [n][2ep+1])    (A of GEMM4, alias Qd)
//   KVd[32][72] : u32(ep,e2) = (KV[2ep][e2], KV[2ep+1][e2])  (B of GEMM4)
// ---------------------------------------------------------------------------
__global__ void __launch_bounds__(256, 2)
k_qpass(const float* __restrict__ Q, const float* __restrict__ Wf,
        const float* __restrict__ bf, float* __restrict__ Out)
{
    extern __shared__ uint32_t sm[];
    uint32_t* QdHi = sm;               // 32*136 = 4352
    uint32_t* QdLo = sm + 4352;
    uint32_t* QFHi = sm;               // 128*36 = 4608 (alias, time-separated)
    uint32_t* QFLo = sm + 4608;
    uint32_t* WbHi = sm + 9216;        // 32*72 = 2304
    uint32_t* WbLo = sm + 11520;
    uint32_t* KVHi = sm + 13824;       // 32*72
    uint32_t* KVLo = sm + 16128;
    float*    bfs  = (float*)(sm + 18432);   // 64 -> total 18496 u32 = 73984 B

    const int p  = blockIdx.y;
    const int n0 = blockIdx.x * 128;
    const int t    = threadIdx.x;
    const int w    = t >> 5;
    const int lane = t & 31;
    const int g    = lane >> 2;
    const int q    = lane & 3;
    const int r0 = w * 16 + g;         // n-row (M dim), warp owns one m16 strip
    const int r1 = r0 + 8;

    // Wb planes (row-contiguous float2 reads of Wf)
    for (int i = t; i < 64 * 32; i += 256) {
        const int e = i >> 5, dp = i & 31;
        float2 f = *(const float2*)&Wf[e * 64 + 2 * dp];
        uint32_t h, l; split2(f.x, f.y, h, l);
        WbHi[dp * 72 + e] = h; WbLo[dp * 72 + e] = l;
    }
    // KVd planes (pack along e)
    for (int i = t; i < 32 * 64; i += 256) {
        const int ep = i >> 6, e2 = i & 63;
        const float a = g_kv[(size_t)p * 4096 + (2 * ep) * 64 + e2];
        const float b = g_kv[(size_t)p * 4096 + (2 * ep + 1) * 64 + e2];
        uint32_t h, l; split2(a, b, h, l);
        KVHi[ep * 72 + e2] = h; KVLo[ep * 72 + e2] = l;
    }
    if (t < 64) bfs[t] = bf[t];

    // Qd planes: pack along d
    const float* Qb = Q + (size_t)p * DD * NSEQ;
    for (int m = t; m < 32 * 32; m += 256) {
        const int dp = m >> 5;
        const int c4 = (m & 31) << 2;
        float4 q0 = *(const float4*)(Qb + (2 * dp)     * NSEQ + n0 + c4);
        float4 q1 = *(const float4*)(Qb + (2 * dp + 1) * NSEQ + n0 + c4);
        uint32_t h[4], l[4];
        split2(q0.x, q1.x, h[0], l[0]);
        split2(q0.y, q1.y, h[1], l[1]);
        split2(q0.z, q1.z, h[2], l[2]);
        split2(q0.w, q1.w, h[3], l[3]);
        *(uint4*)&QdHi[dp * 136 + c4] = make_uint4(h[0], h[1], h[2], h[3]);
        *(uint4*)&QdLo[dp * 136 + c4] = make_uint4(l[0], l[1], l[2], l[3]);
    }
    __syncthreads();

    // ---- GEMM3: QF^T = Q^T @ Wf^T (M=128, N=64, K=64) ----
    float acc[8][4];
    #pragma unroll
    for (int i = 0; i < 8; ++i)
        #pragma unroll
        for (int j = 0; j < 4; ++j) acc[i][j] = 0.f;

    #pragma unroll
    for (int ks = 0; ks < 4; ++ks) {
        const int dp0 = ks * 8 + q;
        uint32_t ah[4], al[4];
        ah[0] = QdHi[dp0 * 136 + r0];       al[0] = QdLo[dp0 * 136 + r0];
        ah[1] = QdHi[dp0 * 136 + r1];       al[1] = QdLo[dp0 * 136 + r1];
        ah[2] = QdHi[(dp0 + 4) * 136 + r0]; al[2] = QdLo[(dp0 + 4) * 136 + r0];
        ah[3] = QdHi[(dp0 + 4) * 136 + r1]; al[3] = QdLo[(dp0 + 4) * 136 + r1];
        #pragma unroll
        for (int nf = 0; nf < 8; ++nf) {
            const int c = nf * 8 + g;   // e index
            uint32_t bh[2], bl[2];
            bh[0] = WbHi[dp0 * 72 + c];       bl[0] = WbLo[dp0 * 72 + c];
            bh[1] = WbHi[(dp0 + 4) * 72 + c]; bl[1] = WbLo[(dp0 + 4) * 72 + c];
            mma3(acc[nf], ah, al, bh, bl);
        }
    }
    __syncthreads();   // all warps done reading Qd before QF overwrites it

    // epilogue: bias (per e = column!) + relu, split, store QF planes
    #pragma unroll
    for (int nf = 0; nf < 8; ++nf) {
        const int e0 = nf * 8 + 2 * q;
        const float b0 = bfs[e0], b1 = bfs[e0 + 1];
        const int ep = nf * 4 + q;
        uint32_t h, l;
        split2(fmaxf(acc[nf][0] + b0, 0.f), fmaxf(acc[nf][1] + b1, 0.f), h, l);
        QFHi[r0 * 36 + ep] = h; QFLo[r0 * 36 + ep] = l;
        split2(fmaxf(acc[nf][2] + b0, 0.f), fmaxf(acc[nf][3] + b1, 0.f), h, l);
        QFHi[r1 * 36 + ep] = h; QFLo[r1 * 36 + ep] = l;
    }
    __syncthreads();

    // ---- GEMM4: O^T = QF^T @ KV (M=128, N=64, K=64) ----
    float o[8][4];
    #pragma unroll
    for (int i = 0; i < 8; ++i)
        #pragma unroll
        for (int j = 0; j < 4; ++j) o[i][j] = 0.f;

    #pragma unroll
    for (int ks = 0; ks < 4; ++ks) {
        const int ep0 = ks * 8 + q;
        uint32_t ah[4], al[4];
        ah[0] = QFHi[r0 * 36 + ep0];     al[0] = QFLo[r0 * 36 + ep0];
        ah[1] = QFHi[r1 * 36 + ep0];     al[1] = QFLo[r1 * 36 + ep0];
        ah[2] = QFHi[r0 * 36 + ep0 + 4]; al[2] = QFLo[r0 * 36 + ep0 + 4];
        ah[3] = QFHi[r1 * 36 + ep0 + 4]; al[3] = QFLo[r1 * 36 + ep0 + 4];
        #pragma unroll
        for (int ef = 0; ef < 8; ++ef) {
            const int c = ef * 8 + g;   // e2 index
            uint32_t bh[2], bl[2];
            bh[0] = KVHi[ep0 * 72 + c];       bl[0] = KVLo[ep0 * 72 + c];
            bh[1] = KVHi[(ep0 + 4) * 72 + c]; bl[1] = KVLo[(ep0 + 4) * 72 + c];
            mma3(o[ef], ah, al, bh, bl);
        }
    }

    // output: O[e2][n] = O^T fragment (rows n = r0/r1, cols e2)
    float* Ob = Out + (size_t)p * DD * NSEQ;
    #pragma unroll
    for (int ef = 0; ef < 8; ++ef) {
        const int e2 = ef * 8 + 2 * q;
        Ob[(size_t)e2 * NSEQ + n0 + r0]       = o[ef][0];
        Ob[(size_t)(e2 + 1) * NSEQ + n0 + r0] = o[ef][1];
        Ob[(size_t)e2 * NSEQ + n0 + r1]       = o[ef][2];
        Ob[(size_t)(e2 + 1) * NSEQ + n0 + r1] = o[ef][3];
    }
}

// ---------------------------------------------------------------------------
// Launch
// ---------------------------------------------------------------------------
extern "C" void kernel_launch(void* const* d_in, const int* in_sizes, int n_in,
                              void* d_out, int out_size)
{
    const float* q  = (const float*)d_in[0];
    const float* k  = (const float*)d_in[1];
    const float* v  = (const float*)d_in[2];
    const float* Wf = (const float*)d_in[3];
    const float* bf = (const float*)d_in[4];
    float* out = (float*)d_out;

    const int SMEM1 = 22080 * (int)sizeof(uint32_t);   // 88320 B
    const int SMEM3 = 18496 * (int)sizeof(uint32_t);   // 73984 B
    cudaFuncSetAttribute(k_kvpass, cudaFuncAttributeMaxDynamicSharedMemorySize, SMEM1);
    cudaFuncSetAttribute(k_qpass,  cudaFuncAttributeMaxDynamicSharedMemorySize, SMEM3);

    k_kvpass<<<dim3(SPLITS, NPAIRS), 256, SMEM1>>>(k, v, Wf, bf);
    k_reduce<<<(NPAIRS * DD * DD) / 256, 256>>>();
    k_qpass<<<dim3(NSEQ / 128, NPAIRS), 256, SMEM3>>>(q, Wf, bf, out);
}